// round 2
// baseline (speedup 1.0000x reference)
#include <cuda_runtime.h>

#define NN 20000
#define EE 100000
#define FNF 92
#define FEF 50
#define DD 64
#define GG 128
#define LL 3

// ---------------- device scratch (no allocations allowed) ----------------
__device__ float  g_h[NN * DD];            // node state (out == GRU hidden)
__device__ float  g_hid[(size_t)EE * DD];  // edge MLP stage-1 output
__device__ float  g_agg[NN * DD];          // scatter-sum of messages
__device__ float  g_m[NN * DD];            // pre-BN conv output
__device__ float  g_cnt[NN];               // in-degree per dst node
__device__ double g_bnsum[DD];
__device__ double g_bnsq[DD];
__device__ float  g_mu[DD];
__device__ float  g_rstd[DD];
__device__ float  g_pool[GG * DD];
__device__ float  g_pcnt[GG];

// ---------------- init / counting ----------------
__global__ void k_init() {
    int i = blockIdx.x * blockDim.x + threadIdx.x;
    if (i < NN) g_cnt[i] = 0.f;
    if (i < GG * DD) g_pool[i] = 0.f;
    if (i < GG) g_pcnt[i] = 0.f;
}

__global__ void k_count(const int* __restrict__ dst, const int* __restrict__ batch) {
    int i = blockIdx.x * blockDim.x + threadIdx.x;
    if (i < EE) atomicAdd(&g_cnt[dst[i]], 1.f);
    if (i < NN) atomicAdd(&g_pcnt[batch[i]], 1.f);
}

__global__ void k_zl() {
    int i = blockIdx.x * blockDim.x + threadIdx.x;
    if (i < NN * DD) g_agg[i] = 0.f;
    if (i < DD) { g_bnsum[i] = 0.0; g_bnsq[i] = 0.0; }
}

// ---------------- pre-FC: h = relu(x @ pre_w + pre_b) ----------------
__global__ void k_pre(const float* __restrict__ x, const float* __restrict__ w,
                      const float* __restrict__ b) {
    __shared__ float xs[4][FNF];
    int tx = threadIdx.x, ty = threadIdx.y;
    int n = blockIdx.x * 4 + ty;
    for (int f = tx; f < FNF; f += 64) xs[ty][f] = x[(size_t)n * FNF + f];
    __syncthreads();
    float acc = b[tx];
#pragma unroll
    for (int f = 0; f < FNF; ++f) acc += xs[ty][f] * w[f * DD + tx];
    g_h[n * DD + tx] = fmaxf(acc, 0.f);
}

// ---------------- edge MLP stage 1: hid = relu(ea @ W1 + b1) ----------------
__global__ void k_hid(const float* __restrict__ ea, const float* __restrict__ w,
                      const float* __restrict__ b) {
    __shared__ float es[4][FEF];
    int tx = threadIdx.x, ty = threadIdx.y;
    int e = blockIdx.x * 4 + ty;
    for (int f = tx; f < FEF; f += 64) es[ty][f] = ea[(size_t)e * FEF + f];
    __syncthreads();
    float acc = b[tx];
#pragma unroll
    for (int f = 0; f < FEF; ++f) acc += es[ty][f] * w[f * DD + tx];
    g_hid[(size_t)e * DD + tx] = fmaxf(acc, 0.f);
}

// ---------------- THE kernel: per-edge rank-1 GEMM + scatter-add ----------------
// msg[e,o] = sum_j hid[e,j] * sum_i u[e,i]*W2[j, i*64+o]  + sum_i u[e,i]*b2[i*64+o]
// Block: 64 edges, 128 threads = (16 o-groups x 8 e-groups), thread tile 8x4.
__global__ void __launch_bounds__(128) k_msg(const int* __restrict__ src,
                                             const int* __restrict__ dst,
                                             const float* __restrict__ W2,
                                             const float* __restrict__ b2) {
    __shared__ float uT[64][64];   // [i][e]
    __shared__ float hT[64][64];   // [j][e]
    __shared__ float Bs[64 * 64];  // [i][o] for current j-chunk
    int tid = threadIdx.x;
    int e0b = blockIdx.x * 64;

    // load u (gathered via src) and hid, transposed into smem
    for (int t = tid; t < 1024; t += 128) {
        int q = t & 15, e = t >> 4;
        int ge = e0b + e;
        float4 uv = make_float4(0.f, 0.f, 0.f, 0.f);
        float4 hv = make_float4(0.f, 0.f, 0.f, 0.f);
        if (ge < EE) {
            int s = src[ge];
            uv = *(const float4*)&g_h[(size_t)s * DD + q * 4];
            hv = *(const float4*)&g_hid[(size_t)ge * DD + q * 4];
        }
        uT[q * 4 + 0][e] = uv.x; uT[q * 4 + 1][e] = uv.y;
        uT[q * 4 + 2][e] = uv.z; uT[q * 4 + 3][e] = uv.w;
        hT[q * 4 + 0][e] = hv.x; hT[q * 4 + 1][e] = hv.y;
        hT[q * 4 + 2][e] = hv.z; hT[q * 4 + 3][e] = hv.w;
    }

    int og = tid & 15, eg = tid >> 4;
    int o0 = og * 4, e0 = eg * 8;

    float acc[8][4];
#pragma unroll
    for (int m = 0; m < 8; m++)
#pragma unroll
        for (int n = 0; n < 4; n++) acc[m][n] = 0.f;

    for (int kc = 0; kc < 65; kc++) {
        __syncthreads();
        const float* rowp = (kc < 64) ? (W2 + (size_t)kc * 4096) : b2;
        for (int t = tid; t < 1024; t += 128)
            *(float4*)&Bs[t * 4] = *(const float4*)&rowp[t * 4];
        __syncthreads();

        float tmp[8][4];
#pragma unroll
        for (int m = 0; m < 8; m++)
#pragma unroll
            for (int n = 0; n < 4; n++) tmp[m][n] = 0.f;

#pragma unroll 8
        for (int i = 0; i < 64; i++) {
            float4 b4 = *(const float4*)&Bs[i * 64 + o0];
            float4 a0 = *(const float4*)&uT[i][e0];
            float4 a1 = *(const float4*)&uT[i][e0 + 4];
            float av[8] = {a0.x, a0.y, a0.z, a0.w, a1.x, a1.y, a1.z, a1.w};
            float bv[4] = {b4.x, b4.y, b4.z, b4.w};
#pragma unroll
            for (int m = 0; m < 8; m++)
#pragma unroll
                for (int n = 0; n < 4; n++) tmp[m][n] += av[m] * bv[n];
        }

        float hv[8];
        if (kc < 64) {
            float4 h0 = *(const float4*)&hT[kc][e0];
            float4 h1 = *(const float4*)&hT[kc][e0 + 4];
            hv[0] = h0.x; hv[1] = h0.y; hv[2] = h0.z; hv[3] = h0.w;
            hv[4] = h1.x; hv[5] = h1.y; hv[6] = h1.z; hv[7] = h1.w;
        } else {
#pragma unroll
            for (int m = 0; m < 8; m++) hv[m] = 1.f;
        }
#pragma unroll
        for (int m = 0; m < 8; m++)
#pragma unroll
            for (int n = 0; n < 4; n++) acc[m][n] += hv[m] * tmp[m][n];
    }

    // scatter-add into agg[dst]
#pragma unroll
    for (int m = 0; m < 8; m++) {
        int ge = e0b + e0 + m;
        if (ge < EE) {
            int dn = dst[ge];
#pragma unroll
            for (int n = 0; n < 4; n++)
                atomicAdd(&g_agg[dn * DD + o0 + n], acc[m][n]);
        }
    }
}

// ---------------- m = agg/deg + h@root + bias; accumulate BN stats ----------------
__global__ void k_bn1(const float* __restrict__ root, const float* __restrict__ cb) {
    __shared__ float hs[4][DD];
    __shared__ float ms[4][DD];
    int tx = threadIdx.x, ty = threadIdx.y;
    int n = blockIdx.x * 4 + ty;
    hs[ty][tx] = g_h[n * DD + tx];
    __syncthreads();
    float c = g_cnt[n];
    float acc = g_agg[n * DD + tx] / fmaxf(c, 1.f) + cb[tx];
#pragma unroll
    for (int d = 0; d < DD; ++d) acc += hs[ty][d] * root[d * DD + tx];
    g_m[n * DD + tx] = acc;
    ms[ty][tx] = acc;
    __syncthreads();
    if (ty == 0) {
        float s  = ms[0][tx] + ms[1][tx] + ms[2][tx] + ms[3][tx];
        float sq = ms[0][tx] * ms[0][tx] + ms[1][tx] * ms[1][tx] +
                   ms[2][tx] * ms[2][tx] + ms[3][tx] * ms[3][tx];
        atomicAdd(&g_bnsum[tx], (double)s);
        atomicAdd(&g_bnsq[tx], (double)sq);
    }
}

__global__ void k_bnfin() {
    int o = threadIdx.x;
    double mu = g_bnsum[o] / (double)NN;
    double var = g_bnsq[o] / (double)NN - mu * mu;
    g_mu[o] = (float)mu;
    g_rstd[o] = rsqrtf((float)var + 1e-5f);
}

// ---------------- BN-apply + relu + GRU cell ----------------
__global__ void k_gru(const float* __restrict__ gamma, const float* __restrict__ beta,
                      const float* __restrict__ wih, const float* __restrict__ whh,
                      const float* __restrict__ bih, const float* __restrict__ bhh) {
    __shared__ float ms[4][DD];
    __shared__ float hs[4][DD];
    int tx = threadIdx.x, ty = threadIdx.y;
    int n = blockIdx.x * 4 + ty;
    float mv = g_m[n * DD + tx];
    mv = gamma[tx] * (mv - g_mu[tx]) * g_rstd[tx] + beta[tx];
    mv = fmaxf(mv, 0.f);
    ms[ty][tx] = mv;
    float hvv = g_h[n * DD + tx];
    hs[ty][tx] = hvv;
    __syncthreads();
    float gr = bih[tx], gz = bih[DD + tx], gn = bih[2 * DD + tx];
    float hr = bhh[tx], hz = bhh[DD + tx], hn = bhh[2 * DD + tx];
#pragma unroll
    for (int d = 0; d < DD; ++d) {
        float md = ms[ty][d], hd = hs[ty][d];
        gr += md * wih[(0 * DD + tx) * DD + d];
        gz += md * wih[(1 * DD + tx) * DD + d];
        gn += md * wih[(2 * DD + tx) * DD + d];
        hr += hd * whh[(0 * DD + tx) * DD + d];
        hz += hd * whh[(1 * DD + tx) * DD + d];
        hn += hd * whh[(2 * DD + tx) * DD + d];
    }
    float r = 1.f / (1.f + __expf(-(gr + hr)));
    float z = 1.f / (1.f + __expf(-(gz + hz)));
    float nn2 = tanhf(gn + r * hn);
    g_h[n * DD + tx] = (1.f - z) * nn2 + z * hvv;
}

// ---------------- pooling + head ----------------
__global__ void k_pool(const int* __restrict__ batch) {
    int i = blockIdx.x * blockDim.x + threadIdx.x;
    if (i >= NN * DD) return;
    int n = i >> 6, o = i & 63;
    atomicAdd(&g_pool[batch[n] * DD + o], g_h[i]);
}

__global__ void k_head(const float* __restrict__ pw, const float* __restrict__ pb,
                       const float* __restrict__ ow, const float* __restrict__ ob,
                       float* __restrict__ out) {
    __shared__ float p[DD];
    __shared__ float q[DD];
    int g = blockIdx.x, o = threadIdx.x;
    p[o] = g_pool[g * DD + o] / fmaxf(g_pcnt[g], 1.f);
    __syncthreads();
    float acc = pb[o];
#pragma unroll
    for (int d = 0; d < DD; ++d) acc += p[d] * pw[d * DD + o];
    q[o] = fmaxf(acc, 0.f) * ow[o];
    __syncthreads();
    if (o == 0) {
        float s = ob[0];
        for (int d = 0; d < DD; ++d) s += q[d];
        out[g] = s;
    }
}

// ---------------- launch ----------------
extern "C" void kernel_launch(void* const* d_in, const int* in_sizes, int n_in,
                              void* d_out, int out_size) {
    const float* x     = (const float*)d_in[0];
    const int*   ei    = (const int*)d_in[1];
    const float* ea    = (const float*)d_in[2];
    const int*   batch = (const int*)d_in[3];
    const float* pre_w = (const float*)d_in[4];
    const float* pre_b = (const float*)d_in[5];
    const float* ew1   = (const float*)d_in[6];
    const float* eb1   = (const float*)d_in[7];
    const float* ew2   = (const float*)d_in[8];
    const float* eb2   = (const float*)d_in[9];
    const float* root  = (const float*)d_in[10];
    const float* cb    = (const float*)d_in[11];
    const float* bng   = (const float*)d_in[12];
    const float* bnb   = (const float*)d_in[13];
    const float* wih   = (const float*)d_in[14];
    const float* whh   = (const float*)d_in[15];
    const float* bih   = (const float*)d_in[16];
    const float* bhh   = (const float*)d_in[17];
    const float* pw    = (const float*)d_in[18];
    const float* pb    = (const float*)d_in[19];
    const float* ow    = (const float*)d_in[20];
    const float* ob    = (const float*)d_in[21];
    float* out = (float*)d_out;
    const int* src = ei;
    const int* dst = ei + EE;

    k_init<<<(NN + 255) / 256, 256>>>();
    k_count<<<(EE + 255) / 256, 256>>>(dst, batch);
    k_pre<<<NN / 4, dim3(64, 4)>>>(x, pre_w, pre_b);

    for (int l = 0; l < LL; l++) {
        k_zl<<<(NN * DD + 255) / 256, 256>>>();
        k_hid<<<EE / 4, dim3(64, 4)>>>(ea, ew1 + (size_t)l * FEF * DD, eb1 + l * DD);
        k_msg<<<(EE + 63) / 64, 128>>>(src, dst,
                                       ew2 + (size_t)l * DD * DD * DD,
                                       eb2 + (size_t)l * DD * DD);
        k_bn1<<<NN / 4, dim3(64, 4)>>>(root + (size_t)l * DD * DD, cb + l * DD);
        k_bnfin<<<1, 64>>>();
        k_gru<<<NN / 4, dim3(64, 4)>>>(bng + l * DD, bnb + l * DD,
                                       wih + (size_t)l * 3 * DD * DD,
                                       whh + (size_t)l * 3 * DD * DD,
                                       bih + (size_t)l * 3 * DD,
                                       bhh + (size_t)l * 3 * DD);
    }

    k_pool<<<(NN * DD + 255) / 256, 256>>>(batch);
    k_head<<<GG, 64>>>(pw, pb, ow, ob, out);
}

// round 4
// speedup vs baseline: 3.9825x; 3.9825x over previous
#include <cuda_runtime.h>

#define NN 20000
#define EE 100000
#define FNF 92
#define FEF 50
#define DD 64
#define GG 128
#define LL 3
#define YW 4160   // 64*64 + 64 bias cols

// ---------------- device scratch (static; no runtime allocation) ----------------
__device__ float  g_h[NN * DD];
__device__ float  g_hid[(size_t)EE * DD];
__device__ float  g_agg[NN * DD];
__device__ float  g_m[NN * DD];
__device__ float  g_cnt[NN];
__device__ double g_bnsum[DD];
__device__ double g_bnsq[DD];
__device__ float  g_mu[DD];
__device__ float  g_rstd[DD];
__device__ float  g_pool[GG * DD];
__device__ float  g_pcnt[GG];
__device__ float  g_Y[(size_t)NN * YW];     // per-node precomputed Y (+bias cols)
__device__ float  g_w2t[64 * YW];           // transposed W2 (+b2) for current layer
__device__ float  g_wihT[192 * DD];
__device__ float  g_whhT[192 * DD];
__device__ int    g_deg[NN];
__device__ int    g_off[NN];
__device__ int    g_rank[EE];
__device__ int    g_eorder[EE];             // edges grouped by src

// ---------------- init / CSR build ----------------
__global__ void k_init() {
    int i = blockIdx.x * blockDim.x + threadIdx.x;
    if (i < NN) { g_cnt[i] = 0.f; g_deg[i] = 0; }
    if (i < GG * DD) g_pool[i] = 0.f;
    if (i < GG) g_pcnt[i] = 0.f;
}

__global__ void k_deg(const int* __restrict__ src, const int* __restrict__ dst,
                      const int* __restrict__ batch) {
    int i = blockIdx.x * blockDim.x + threadIdx.x;
    if (i < EE) {
        g_rank[i] = atomicAdd(&g_deg[src[i]], 1);
        atomicAdd(&g_cnt[dst[i]], 1.f);
    }
    if (i < NN) atomicAdd(&g_pcnt[batch[i]], 1.f);
}

__global__ void k_scan() {   // single-block exclusive scan of g_deg -> g_off
    __shared__ int s[1024];
    __shared__ int carry;
    int tid = threadIdx.x;
    if (tid == 0) carry = 0;
    __syncthreads();
    for (int base = 0; base < NN; base += 1024) {
        int v = (base + tid < NN) ? g_deg[base + tid] : 0;
        s[tid] = v;
        __syncthreads();
        for (int off = 1; off < 1024; off <<= 1) {
            int t = (tid >= off) ? s[tid - off] : 0;
            __syncthreads();
            s[tid] += t;
            __syncthreads();
        }
        if (base + tid < NN) g_off[base + tid] = carry + s[tid] - v;
        __syncthreads();
        if (tid == 0) carry += s[1023];
        __syncthreads();
    }
}

__global__ void k_perm(const int* __restrict__ src) {
    int e = blockIdx.x * blockDim.x + threadIdx.x;
    if (e < EE) g_eorder[g_off[src[e]] + g_rank[e]] = e;
}

__global__ void k_zl() {
    int i = blockIdx.x * blockDim.x + threadIdx.x;
    if (i < NN * DD) g_agg[i] = 0.f;
    if (i < DD) { g_bnsum[i] = 0.0; g_bnsq[i] = 0.0; }
}

// ---------------- pre-FC ----------------
__global__ void k_pre(const float* __restrict__ x, const float* __restrict__ w,
                      const float* __restrict__ b) {
    __shared__ float xs[4][FNF];
    int tx = threadIdx.x, ty = threadIdx.y;
    int n = blockIdx.x * 4 + ty;
    for (int f = tx; f < FNF; f += 64) xs[ty][f] = x[(size_t)n * FNF + f];
    __syncthreads();
    float acc = b[tx];
#pragma unroll
    for (int f = 0; f < FNF; ++f) acc += xs[ty][f] * w[f * DD + tx];
    g_h[n * DD + tx] = fmaxf(acc, 0.f);
}

// ---------------- edge MLP stage 1 ----------------
__global__ void k_hid(const float* __restrict__ ea, const float* __restrict__ w,
                      const float* __restrict__ b) {
    __shared__ float es[4][FEF];
    int tx = threadIdx.x, ty = threadIdx.y;
    int e = blockIdx.x * 4 + ty;
    for (int f = tx; f < FEF; f += 64) es[ty][f] = ea[(size_t)e * FEF + f];
    __syncthreads();
    float acc = b[tx];
#pragma unroll
    for (int f = 0; f < FEF; ++f) acc += es[ty][f] * w[f * DD + tx];
    g_hid[(size_t)e * DD + tx] = fmaxf(acc, 0.f);
}

// ---------------- W2 transpose (+ b2 folded as cols 4096..4159) ----------------
__global__ void k_w2t(const float* __restrict__ W2, const float* __restrict__ b2) {
    int t = blockIdx.x * blockDim.x + threadIdx.x;
    if (t >= 64 * YW) return;
    int i = t / YW, col = t % YW;
    float v;
    if (col < 4096) {
        int j = col >> 6, o = col & 63;
        v = W2[j * 4096 + i * 64 + o];
    } else {
        v = b2[i * 64 + (col - 4096)];
    }
    g_w2t[t] = v;
}

// ---------------- GRU weight transpose ----------------
__global__ void k_wtr(const float* __restrict__ wih, const float* __restrict__ whh) {
    int t = blockIdx.x * blockDim.x + threadIdx.x;
    if (t >= 192 * DD) return;
    int d = t / 192, k = t % 192;
    g_wihT[t] = wih[k * DD + d];
    g_whhT[t] = whh[k * DD + d];
}

// ---------------- Y GEMM: g_Y[n, :] = g_h[n, :] @ g_w2t ----------------
// smem tile padded to 68 floats/row: multiple of 4 (float4-aligned LDS.128)
// and 68 % 32 != 0 so the scalar transpose-writes spread across banks.
__global__ void __launch_bounds__(256) k_ygemm() {
    __shared__ float hsT[64][68];
    int tid = threadIdx.x;
    int mb = blockIdx.x * 64;
    int nb = blockIdx.y * 256;
    for (int t = tid; t < 1024; t += 256) {
        int m = t >> 4, q = t & 15;
        int gm = mb + m;
        float4 v = make_float4(0.f, 0.f, 0.f, 0.f);
        if (gm < NN) v = *(const float4*)&g_h[gm * DD + q * 4];
        hsT[q * 4 + 0][m] = v.x; hsT[q * 4 + 1][m] = v.y;
        hsT[q * 4 + 2][m] = v.z; hsT[q * 4 + 3][m] = v.w;
    }
    __syncthreads();
    int mg = tid >> 5, ng = tid & 31;
    int m0 = mg * 8;
    int n0 = nb + ng * 8;
    if (n0 >= YW) return;
    float acc[8][8];
#pragma unroll
    for (int a = 0; a < 8; a++)
#pragma unroll
        for (int b = 0; b < 8; b++) acc[a][b] = 0.f;
    const float* Bp = g_w2t + n0;
#pragma unroll 4
    for (int k = 0; k < 64; k++) {
        float4 a0 = *(const float4*)&hsT[k][m0];
        float4 a1 = *(const float4*)&hsT[k][m0 + 4];
        float4 b0 = *(const float4*)&Bp[k * YW];
        float4 b1 = *(const float4*)&Bp[k * YW + 4];
        float av[8] = {a0.x, a0.y, a0.z, a0.w, a1.x, a1.y, a1.z, a1.w};
        float bv[8] = {b0.x, b0.y, b0.z, b0.w, b1.x, b1.y, b1.z, b1.w};
#pragma unroll
        for (int mm = 0; mm < 8; mm++)
#pragma unroll
            for (int nn = 0; nn < 8; nn++) acc[mm][nn] += av[mm] * bv[nn];
    }
#pragma unroll
    for (int mm = 0; mm < 8; mm++) {
        int gm = mb + m0 + mm;
        if (gm >= NN) continue;
        float* Cp = g_Y + (size_t)gm * YW + n0;
        *(float4*)Cp       = make_float4(acc[mm][0], acc[mm][1], acc[mm][2], acc[mm][3]);
        *(float4*)(Cp + 4) = make_float4(acc[mm][4], acc[mm][5], acc[mm][6], acc[mm][7]);
    }
}

// ---------------- edge phase: msg[e,o] = hid[e,:] @ Y[src[e]] + bias; scatter ----------------
__global__ void __launch_bounds__(256) k_edge(const int* __restrict__ src,
                                              const int* __restrict__ dst) {
    __shared__ float hid_s[32][64];
    __shared__ int ssrc[32], sdst[32], seo[32];
    int tid = threadIdx.x;
    int eb0 = blockIdx.x * 32;
    if (tid < 32) {
        int eo = g_eorder[eb0 + tid];
        seo[tid] = eo;
        ssrc[tid] = src[eo];
        sdst[tid] = dst[eo];
    }
    __syncthreads();
    for (int t = tid; t < 32 * 16; t += 256) {
        int el = t >> 4, q = t & 15;
        *(float4*)&hid_s[el][q * 4] = *(const float4*)&g_hid[(size_t)seo[el] * DD + q * 4];
    }
    __syncthreads();
    int o4 = (tid & 15) * 4;
    int el0 = tid >> 4;
#pragma unroll
    for (int m = 0; m < 2; m++) {
        int el = el0 + 16 * m;
        const float* Yr = g_Y + (size_t)ssrc[el] * YW;
        float4 acc = *(const float4*)&Yr[4096 + o4];
#pragma unroll 8
        for (int j = 0; j < 64; j++) {
            float hj = hid_s[el][j];
            float4 yv = *(const float4*)&Yr[j * 64 + o4];
            acc.x += hj * yv.x; acc.y += hj * yv.y;
            acc.z += hj * yv.z; acc.w += hj * yv.w;
        }
        float* ap = g_agg + (size_t)sdst[el] * DD + o4;
        atomicAdd(ap + 0, acc.x); atomicAdd(ap + 1, acc.y);
        atomicAdd(ap + 2, acc.z); atomicAdd(ap + 3, acc.w);
    }
}

// ---------------- conv combine + BN stats ----------------
__global__ void k_bn1(const float* __restrict__ root, const float* __restrict__ cb) {
    __shared__ float hs[4][DD];
    __shared__ float ms[4][DD];
    int tx = threadIdx.x, ty = threadIdx.y;
    int n = blockIdx.x * 4 + ty;
    hs[ty][tx] = g_h[n * DD + tx];
    __syncthreads();
    float c = g_cnt[n];
    float acc = g_agg[n * DD + tx] / fmaxf(c, 1.f) + cb[tx];
#pragma unroll
    for (int d = 0; d < DD; ++d) acc += hs[ty][d] * root[d * DD + tx];
    g_m[n * DD + tx] = acc;
    ms[ty][tx] = acc;
    __syncthreads();
    if (ty == 0) {
        float s  = ms[0][tx] + ms[1][tx] + ms[2][tx] + ms[3][tx];
        float sq = ms[0][tx] * ms[0][tx] + ms[1][tx] * ms[1][tx] +
                   ms[2][tx] * ms[2][tx] + ms[3][tx] * ms[3][tx];
        atomicAdd(&g_bnsum[tx], (double)s);
        atomicAdd(&g_bnsq[tx], (double)sq);
    }
}

__global__ void k_bnfin() {
    int o = threadIdx.x;
    double mu = g_bnsum[o] / (double)NN;
    double var = g_bnsq[o] / (double)NN - mu * mu;
    g_mu[o] = (float)mu;
    g_rstd[o] = rsqrtf((float)var + 1e-5f);
}

// ---------------- BN-apply + relu + GRU ----------------
__global__ void k_gru(const float* __restrict__ gamma, const float* __restrict__ beta,
                      const float* __restrict__ bih, const float* __restrict__ bhh) {
    __shared__ float ms[4][DD];
    __shared__ float hs[4][DD];
    int tx = threadIdx.x, ty = threadIdx.y;
    int n = blockIdx.x * 4 + ty;
    float mv = g_m[n * DD + tx];
    mv = gamma[tx] * (mv - g_mu[tx]) * g_rstd[tx] + beta[tx];
    mv = fmaxf(mv, 0.f);
    ms[ty][tx] = mv;
    float hvv = g_h[n * DD + tx];
    hs[ty][tx] = hvv;
    __syncthreads();
    float gr = bih[tx], gz = bih[DD + tx], gn = bih[2 * DD + tx];
    float hr = bhh[tx], hz = bhh[DD + tx], hn = bhh[2 * DD + tx];
#pragma unroll
    for (int d = 0; d < DD; ++d) {
        float md = ms[ty][d], hd = hs[ty][d];
        const float* wT = g_wihT + d * 192;
        const float* vT = g_whhT + d * 192;
        gr += md * wT[tx];       gz += md * wT[64 + tx];  gn += md * wT[128 + tx];
        hr += hd * vT[tx];       hz += hd * vT[64 + tx];  hn += hd * vT[128 + tx];
    }
    float r = 1.f / (1.f + __expf(-(gr + hr)));
    float z = 1.f / (1.f + __expf(-(gz + hz)));
    float nn2 = tanhf(gn + r * hn);
    g_h[n * DD + tx] = (1.f - z) * nn2 + z * hvv;
}

// ---------------- pooling + head ----------------
__global__ void k_pool(const int* __restrict__ batch) {
    int i = blockIdx.x * blockDim.x + threadIdx.x;
    if (i >= NN * DD) return;
    int n = i >> 6, o = i & 63;
    atomicAdd(&g_pool[batch[n] * DD + o], g_h[i]);
}

__global__ void k_head(const float* __restrict__ pw, const float* __restrict__ pb,
                       const float* __restrict__ ow, const float* __restrict__ ob,
                       float* __restrict__ out) {
    __shared__ float p[DD];
    __shared__ float q[DD];
    int g = blockIdx.x, o = threadIdx.x;
    p[o] = g_pool[g * DD + o] / fmaxf(g_pcnt[g], 1.f);
    __syncthreads();
    float acc = pb[o];
#pragma unroll
    for (int d = 0; d < DD; ++d) acc += p[d] * pw[d * DD + o];
    q[o] = fmaxf(acc, 0.f) * ow[o];
    __syncthreads();
    if (o == 0) {
        float s = ob[0];
        for (int d = 0; d < DD; ++d) s += q[d];
        out[g] = s;
    }
}

// ---------------- launch ----------------
extern "C" void kernel_launch(void* const* d_in, const int* in_sizes, int n_in,
                              void* d_out, int out_size) {
    const float* x     = (const float*)d_in[0];
    const int*   ei    = (const int*)d_in[1];
    const float* ea    = (const float*)d_in[2];
    const int*   batch = (const int*)d_in[3];
    const float* pre_w = (const float*)d_in[4];
    const float* pre_b = (const float*)d_in[5];
    const float* ew1   = (const float*)d_in[6];
    const float* eb1   = (const float*)d_in[7];
    const float* ew2   = (const float*)d_in[8];
    const float* eb2   = (const float*)d_in[9];
    const float* root  = (const float*)d_in[10];
    const float* cb    = (const float*)d_in[11];
    const float* bng   = (const float*)d_in[12];
    const float* bnb   = (const float*)d_in[13];
    const float* wih   = (const float*)d_in[14];
    const float* whh   = (const float*)d_in[15];
    const float* bih   = (const float*)d_in[16];
    const float* bhh   = (const float*)d_in[17];
    const float* pw    = (const float*)d_in[18];
    const float* pb    = (const float*)d_in[19];
    const float* ow    = (const float*)d_in[20];
    const float* ob    = (const float*)d_in[21];
    float* out = (float*)d_out;
    const int* src = ei;
    const int* dst = ei + EE;

    k_init<<<(NN + 255) / 256, 256>>>();
    k_deg<<<(EE + 255) / 256, 256>>>(src, dst, batch);
    k_scan<<<1, 1024>>>();
    k_perm<<<(EE + 255) / 256, 256>>>(src);
    k_pre<<<NN / 4, dim3(64, 4)>>>(x, pre_w, pre_b);

    for (int l = 0; l < LL; l++) {
        k_zl<<<(NN * DD + 255) / 256, 256>>>();
        k_hid<<<EE / 4, dim3(64, 4)>>>(ea, ew1 + (size_t)l * FEF * DD, eb1 + l * DD);
        k_w2t<<<(64 * YW + 255) / 256, 256>>>(ew2 + (size_t)l * DD * DD * DD,
                                              eb2 + (size_t)l * DD * DD);
        k_wtr<<<(192 * DD + 255) / 256, 256>>>(wih + (size_t)l * 3 * DD * DD,
                                               whh + (size_t)l * 3 * DD * DD);
        k_ygemm<<<dim3((NN + 63) / 64, (YW + 255) / 256), 256>>>();
        k_edge<<<EE / 32, 256>>>(src, dst);
        k_bn1<<<NN / 4, dim3(64, 4)>>>(root + (size_t)l * DD * DD, cb + l * DD);
        k_bnfin<<<1, 64>>>();
        k_gru<<<NN / 4, dim3(64, 4)>>>(bng + l * DD, bnb + l * DD,
                                       bih + (size_t)l * 3 * DD,
                                       bhh + (size_t)l * 3 * DD);
    }

    k_pool<<<(NN * DD + 255) / 256, 256>>>(batch);
    k_head<<<GG, 64>>>(pw, pb, ow, ob, out);
}